// round 12
// baseline (speedup 1.0000x reference)
#include <cuda_runtime.h>
#include <cuda_bf16.h>
#include <mma.h>
#include <math.h>
#include <stdint.h>

using namespace nvcuda;

#define Gn 512
#define Pn 128
#define Dn 256
#define En 1024
#define Hn 8
#define HDn 32
#define DFn 1024
#define Mn (Gn*Pn)

typedef unsigned long long u64t;

// ---------------- scratch ----------------
__device__ float g_h[(size_t)Mn*Dn];
__device__ float g_tmp[(size_t)Mn*Dn];
__device__ float g_qkv[(size_t)Mn*3*Dn];
__device__ __nv_bfloat16 g_as1[(size_t)Mn*2*Dn];
__device__ __nv_bfloat16 g_as2[(size_t)Mn*2*DFn];

// packed weights: [N][2K] bf16 = hi | lo
#define W2_CONV   (Dn*2*Dn)                   // 131072
#define W2_FFN    (DFn*2*Dn)                  // 524288
#define W2_LAYER  (4*W2_CONV + 2*W2_FFN)
__device__ __nv_bfloat16 g_w2[2*W2_CONV + 2*W2_LAYER];

__device__ int   g_rp[Pn+1];
__device__ int   g_ci[En+Pn];
__device__ float g_wv[En+Pn];

// ---------------- helpers ----------------
__device__ __forceinline__ uint32_t smem_u32(const void* p) {
    uint32_t a;
    asm("{ .reg .u64 t; cvta.to.shared.u64 t, %1; cvt.u32.u64 %0, t; }" : "=r"(a) : "l"(p));
    return a;
}
__device__ __forceinline__ void cp_async16(uint32_t dst, const void* src) {
    asm volatile("cp.async.cg.shared.global [%0], [%1], 16;" :: "r"(dst), "l"(src) : "memory");
}
__device__ __forceinline__ void cp_commit() {
    asm volatile("cp.async.commit_group;" ::: "memory");
}
template<int N>
__device__ __forceinline__ void cp_wait() {
    asm volatile("cp.async.wait_group %0;" :: "n"(N) : "memory");
}
__device__ __forceinline__ u64t f2pack(float lo, float hi) {
    u64t r; asm("mov.b64 %0, {%1, %2};" : "=l"(r) : "f"(lo), "f"(hi)); return r;
}
__device__ __forceinline__ float2 f2unpack(u64t v) {
    float x, y; asm("mov.b64 {%0, %1}, %2;" : "=f"(x), "=f"(y) : "l"(v));
    return make_float2(x, y);
}
__device__ __forceinline__ u64t fma2(u64t a, u64t b, u64t c) {
    u64t d; asm("fma.rn.f32x2 %0, %1, %2, %3;" : "=l"(d) : "l"(a), "l"(b), "l"(c)); return d;
}
__device__ __forceinline__ void split2(float a, float b, __nv_bfloat162& hi, __nv_bfloat162& lo) {
    hi = __floats2bfloat162_rn(a, b);
    float2 f = __bfloat1622float2(hi);
    lo = __floats2bfloat162_rn(a - f.x, b - f.y);
}

// ---------------- fused graph setup (1 block) ----------------
__global__ void k_setup(const int* __restrict__ ei, int* rp, int* ci, float* wv) {
    __shared__ int   deg[Pn];
    __shared__ float dinv[Pn];
    __shared__ int   srp[Pn+1];
    __shared__ int   cur[Pn];
    int t = threadIdx.x;   // 128
    deg[t] = 1;
    __syncthreads();
    for (int e = t; e < En; e += Pn) atomicAdd(&deg[ei[En + e]], 1);
    __syncthreads();
    dinv[t] = rsqrtf((float)deg[t]);
    __syncthreads();
    if (t == 0) {
        int s = 0;
        for (int i = 0; i < Pn; i++) { srp[i] = s; cur[i] = s; s += deg[i]; }
        srp[Pn] = s;
    }
    __syncthreads();
    for (int e = t; e < En; e += Pn) {
        int s = ei[e], d = ei[En + e];
        int pos = atomicAdd(&cur[d], 1);
        ci[pos] = s; wv[pos] = dinv[s]*dinv[d];
    }
    {   // self loops
        int pos = atomicAdd(&cur[t], 1);
        ci[pos] = t; wv[pos] = dinv[t]*dinv[t];
    }
    rp[t] = srp[t];
    if (t == 0) rp[Pn] = srp[Pn];
}

// ---------------- fused weight pack: W[K,N] fp32 -> [N][2K] hi|lo ----------
struct WD { const float* src; long long dst; int K; int N; };
struct WPack { WD d[14]; long long start[15]; };

__global__ void k_wprepAll(WPack p) {
    long long idx = (long long)blockIdx.x*256 + threadIdx.x;
    if (idx >= p.start[14]) return;
    int r = 0;
    #pragma unroll
    for (int i = 1; i < 14; i++) if (idx >= p.start[i]) r = i;
    long long local = idx - p.start[r];
    const WD d = p.d[r];
    int k = (int)(local / d.N), n = (int)(local - (long long)k*d.N);
    float a = d.src[local];
    __nv_bfloat16 h = __float2bfloat16_rn(a);
    __nv_bfloat16 l = __float2bfloat16_rn(a - __bfloat162float(h));
    __nv_bfloat16* O = g_w2 + d.dst + (size_t)n*2*d.K;
    O[k]       = h;
    O[d.K + k] = l;
}

// ---------------- input split: X[M,256] fp32 -> S[M,512] bf16 ---------------
__global__ void k_asplit(const float* __restrict__ X, __nv_bfloat16* __restrict__ S) {
    int idx = blockIdx.x*blockDim.x + threadIdx.x;
    int row = idx >> 6;
    int g   = (idx & 63) * 4;
    float4 v = reinterpret_cast<const float4*>(X)[idx];
    __nv_bfloat162 h01, l01, h23, l23;
    split2(v.x, v.y, h01, l01);
    split2(v.z, v.w, h23, l23);
    __nv_bfloat16* hp = S + (size_t)row*512 + g;
    *reinterpret_cast<__nv_bfloat162*>(hp)     = h01;
    *reinterpret_cast<__nv_bfloat162*>(hp + 2) = h23;
    *reinterpret_cast<__nv_bfloat162*>(hp + 256)     = l01;
    *reinterpret_cast<__nv_bfloat162*>(hp + 256 + 2) = l23;
}

// ---------------- WMMA GEMM, 3-product split, 3-stage pipeline --------------
// Combined hi|lo tiles: [128 rows][72 elems] pitch 144B (hi cols 0-31, lo 32-63).
// 144 % 16 == 0 (cp.async aligned); row banks advance 4/row -> ldsm conflict-free.
#define TSTR 72
#define TILE_B 18432             // 128*144 bytes
#define STAGE_B (2*TILE_B)       // 36864 (A tile + B tile)
#define GEMM_SMEM (3*STAGE_B)    // 110592 >= epilogue 128*136*4 = 69632

template<int BMODE, bool RELU, bool WF32, bool WSPLIT>
__global__ void __launch_bounds__(256, 2)
gemm_tc(const __nv_bfloat16* __restrict__ A2, long long lda,
        const __nv_bfloat16* __restrict__ B2, long long ldb,
        const float* __restrict__ b0, const float* __restrict__ b1p,
        const float* __restrict__ b2p,
        float* __restrict__ C, __nv_bfloat16* __restrict__ Csp,
        int K, int Ntot)
{
    extern __shared__ __align__(128) char dsm[];
    const int tid = threadIdx.x;
    const int wid = tid >> 5;
    const int wm = wid & 1;       // 0..1  (64-row slice)
    const int wn = wid >> 1;      // 0..3  (32-col slice)
    const int m0 = blockIdx.y * 128;
    const int n0 = blockIdx.x * 128;
    uint32_t sbase = smem_u32(dsm);

    const int nc = K >> 5;

    wmma::fragment<wmma::accumulator, 16,16,16, float> acc[4][2];
    #pragma unroll
    for (int i = 0; i < 4; i++)
        #pragma unroll
        for (int j = 0; j < 2; j++) wmma::fill_fragment(acc[i][j], 0.f);

    // tile layout per stage: A[128][72] then B[128][72]; hi at col 0, lo at col 32
    auto load_chunk = [&](int c, int stage) {
        int k0 = c << 5;
        uint32_t baseA = sbase + stage*STAGE_B;
        uint32_t baseB = baseA + TILE_B;
        #pragma unroll
        for (int r = 0; r < 4; r++) {
            int id = tid + r*256;          // 0..1023
            int row = id >> 3, seg = id & 7;
            int col = (seg < 4) ? (k0 + seg*8) : (K + k0 + (seg-4)*8);
            uint32_t soff = row*144 + seg*16;
            cp_async16(baseA + soff, A2 + (size_t)(m0+row)*lda + col);
            cp_async16(baseB + soff, B2 + (size_t)(n0+row)*ldb + col);
        }
        cp_commit();
    };

    load_chunk(0, 0);
    load_chunk(1, 1);

    for (int c = 0; c < nc; c++) {
        int stage = c % 3;
        if (c + 1 < nc) cp_wait<1>();
        else            cp_wait<0>();
        __syncthreads();
        if (c + 2 < nc) load_chunk(c+2, (c+2) % 3);

        const __nv_bfloat16* At = reinterpret_cast<const __nv_bfloat16*>(dsm + stage*STAGE_B);
        const __nv_bfloat16* Bt = At + TILE_B/2;   // elems

        #pragma unroll
        for (int ks = 0; ks < 2; ks++) {
            wmma::fragment<wmma::matrix_b, 16,16,16, __nv_bfloat16, wmma::col_major> bh[2], bl[2];
            #pragma unroll
            for (int nt = 0; nt < 2; nt++) {
                wmma::load_matrix_sync(bh[nt], Bt + (wn*32 + nt*16)*TSTR + ks*16, TSTR);
                wmma::load_matrix_sync(bl[nt], Bt + (wn*32 + nt*16)*TSTR + 32 + ks*16, TSTR);
            }
            {   // A-hi sweep: hi*hi then hi*lo
                wmma::fragment<wmma::matrix_a, 16,16,16, __nv_bfloat16, wmma::row_major> af[4];
                #pragma unroll
                for (int mt = 0; mt < 4; mt++)
                    wmma::load_matrix_sync(af[mt], At + (wm*64 + mt*16)*TSTR + ks*16, TSTR);
                #pragma unroll
                for (int mt = 0; mt < 4; mt++)
                    #pragma unroll
                    for (int nt = 0; nt < 2; nt++)
                        wmma::mma_sync(acc[mt][nt], af[mt], bh[nt], acc[mt][nt]);
                #pragma unroll
                for (int mt = 0; mt < 4; mt++)
                    #pragma unroll
                    for (int nt = 0; nt < 2; nt++)
                        wmma::mma_sync(acc[mt][nt], af[mt], bl[nt], acc[mt][nt]);
            }
            {   // A-lo sweep: lo*hi
                wmma::fragment<wmma::matrix_a, 16,16,16, __nv_bfloat16, wmma::row_major> af[4];
                #pragma unroll
                for (int mt = 0; mt < 4; mt++)
                    wmma::load_matrix_sync(af[mt], At + (wm*64 + mt*16)*TSTR + 32 + ks*16, TSTR);
                #pragma unroll
                for (int mt = 0; mt < 4; mt++)
                    #pragma unroll
                    for (int nt = 0; nt < 2; nt++)
                        wmma::mma_sync(acc[mt][nt], af[mt], bh[nt], acc[mt][nt]);
            }
        }
    }
    __syncthreads();

    // bias pointer
    const float* bp = nullptr;
    int bbase = 0;
    if (BMODE == 1) { bp = b0; bbase = n0; }
    if (BMODE == 2) {
        int sel = blockIdx.x >> 1;
        bp = (sel == 0) ? b0 : ((sel == 1) ? b1p : b2p);
        bbase = (blockIdx.x & 1) * 128;
    }

    // epilogue: smem-staged, one pass (stride 136 floats, conflict-free)
    float* stg = reinterpret_cast<float*>(dsm);
    #pragma unroll
    for (int mt = 0; mt < 4; mt++)
        #pragma unroll
        for (int nt = 0; nt < 2; nt++)
            wmma::store_matrix_sync(stg + (wm*64 + mt*16)*136 + wn*32 + nt*16,
                                    acc[mt][nt], 136, wmma::mem_row_major);
    __syncthreads();

    int row = tid >> 1;
    int cb  = (tid & 1) * 64;
    const float* sr = stg + row*136 + cb;
    size_t crow  = (size_t)(m0+row)*Ntot + n0 + cb;
    size_t shrow = (size_t)(m0+row)*(2*(size_t)Ntot) + n0 + cb;
    #pragma unroll
    for (int j = 0; j < 64; j += 4) {
        float4 v = *reinterpret_cast<const float4*>(sr + j);
        if (BMODE) {
            float4 b = *reinterpret_cast<const float4*>(bp + bbase + cb + j);
            v.x += b.x; v.y += b.y; v.z += b.z; v.w += b.w;
        }
        if (RELU) {
            v.x = fmaxf(v.x, 0.f); v.y = fmaxf(v.y, 0.f);
            v.z = fmaxf(v.z, 0.f); v.w = fmaxf(v.w, 0.f);
        }
        if (WF32) *reinterpret_cast<float4*>(C + crow + j) = v;
        if (WSPLIT) {
            __nv_bfloat162 h01, l01, h23, l23;
            split2(v.x, v.y, h01, l01);
            split2(v.z, v.w, h23, l23);
            __nv_bfloat16* hp = Csp + shrow + j;
            *reinterpret_cast<__nv_bfloat162*>(hp)     = h01;
            *reinterpret_cast<__nv_bfloat162*>(hp + 2) = h23;
            *reinterpret_cast<__nv_bfloat162*>(hp + Ntot)     = l01;
            *reinterpret_cast<__nv_bfloat162*>(hp + Ntot + 2) = l23;
        }
    }
}

// ---------------- sparse GCN aggregation (+bias +relu) ----------------------
template<bool WF32>
__global__ void __launch_bounds__(256)
agg_csr(const float* __restrict__ xw, const int* __restrict__ rp,
        const int* __restrict__ ci, const float* __restrict__ wv,
        const float* __restrict__ bias, float* __restrict__ outf,
        __nv_bfloat16* __restrict__ sp)
{
    int warp = blockIdx.x*8 + (threadIdx.x >> 5);
    int lane = threadIdx.x & 31;
    int p = warp & 127;
    size_t gbase = (size_t)(warp & ~127) * Dn;

    float4 a0 = make_float4(0.f,0.f,0.f,0.f);
    float4 a1 = make_float4(0.f,0.f,0.f,0.f);
    int s0 = rp[p], s1 = rp[p+1];
    for (int e = s0; e < s1; e++) {
        int src = ci[e]; float w = wv[e];
        const float4* rowp = reinterpret_cast<const float4*>(xw + gbase + (size_t)src*Dn);
        float4 x0 = rowp[lane];
        float4 x1 = rowp[lane+32];
        a0.x = fmaf(w, x0.x, a0.x); a0.y = fmaf(w, x0.y, a0.y);
        a0.z = fmaf(w, x0.z, a0.z); a0.w = fmaf(w, x0.w, a0.w);
        a1.x = fmaf(w, x1.x, a1.x); a1.y = fmaf(w, x1.y, a1.y);
        a1.z = fmaf(w, x1.z, a1.z); a1.w = fmaf(w, x1.w, a1.w);
    }
    int c0 = lane*4;
    float4 b0 = *reinterpret_cast<const float4*>(bias + c0);
    float4 b1 = *reinterpret_cast<const float4*>(bias + c0 + 128);
    a0.x = fmaxf(a0.x + b0.x, 0.f); a0.y = fmaxf(a0.y + b0.y, 0.f);
    a0.z = fmaxf(a0.z + b0.z, 0.f); a0.w = fmaxf(a0.w + b0.w, 0.f);
    a1.x = fmaxf(a1.x + b1.x, 0.f); a1.y = fmaxf(a1.y + b1.y, 0.f);
    a1.z = fmaxf(a1.z + b1.z, 0.f); a1.w = fmaxf(a1.w + b1.w, 0.f);

    if (WF32) {
        float* dst = outf + (size_t)warp*Dn;
        *reinterpret_cast<float4*>(dst + c0)       = a0;
        *reinterpret_cast<float4*>(dst + c0 + 128) = a1;
    }
    __nv_bfloat16* sprow = sp + (size_t)warp*512;
    __nv_bfloat162 h01, l01, h23, l23;
    split2(a0.x, a0.y, h01, l01); split2(a0.z, a0.w, h23, l23);
    *reinterpret_cast<__nv_bfloat162*>(sprow + c0)     = h01;
    *reinterpret_cast<__nv_bfloat162*>(sprow + c0 + 2) = h23;
    *reinterpret_cast<__nv_bfloat162*>(sprow + 256 + c0)     = l01;
    *reinterpret_cast<__nv_bfloat162*>(sprow + 256 + c0 + 2) = l23;
    split2(a1.x, a1.y, h01, l01); split2(a1.z, a1.w, h23, l23);
    *reinterpret_cast<__nv_bfloat162*>(sprow + c0 + 128)     = h01;
    *reinterpret_cast<__nv_bfloat162*>(sprow + c0 + 130)     = h23;
    *reinterpret_cast<__nv_bfloat162*>(sprow + 256 + c0 + 128) = l01;
    *reinterpret_cast<__nv_bfloat162*>(sprow + 256 + c0 + 130) = l23;
}

// ---------------- attention: f32x2-packed, one CTA per (head, graph) -------
__global__ void __launch_bounds__(128)
attn_kernel(const float* __restrict__ qkv, __nv_bfloat16* __restrict__ sp)
{
    int head = blockIdx.x;
    int g    = blockIdx.y;
    int tid  = threadIdx.x;

    __shared__ u64t Ks[Pn][HDn/2];
    __shared__ u64t Vs[Pn][HDn/2];

    size_t base = ((size_t)g*Pn + tid)*768 + head*HDn;
    u64t qr[HDn/2];
    #pragma unroll
    for (int j = 0; j < HDn/4; j++) {
        float4 qv = reinterpret_cast<const float4*>(qkv + base)[j];
        float4 kv = reinterpret_cast<const float4*>(qkv + base + 256)[j];
        float4 vv = reinterpret_cast<const float4*>(qkv + base + 512)[j];
        qr[2*j]   = f2pack(qv.x, qv.y);
        qr[2*j+1] = f2pack(qv.z, qv.w);
        Ks[tid][2*j]   = f2pack(kv.x, kv.y);
        Ks[tid][2*j+1] = f2pack(kv.z, kv.w);
        Vs[tid][2*j]   = f2pack(vv.x, vv.y);
        Vs[tid][2*j+1] = f2pack(vv.z, vv.w);
    }
    __syncthreads();

    const float scale = 0.17677669529663687f;   // 1/sqrt(32)
    float l = 0.f;
    u64t acc[HDn/2];
    #pragma unroll
    for (int d = 0; d < HDn/2; d++) acc[d] = 0ull;

    for (int j = 0; j < Pn; j++) {
        u64t s2 = 0ull;
        #pragma unroll
        for (int d = 0; d < HDn/2; d++) s2 = fma2(qr[d], Ks[j][d], s2);
        float2 sv = f2unpack(s2);
        float e = __expf((sv.x + sv.y)*scale);
        l += e;
        u64t ee = f2pack(e, e);
        #pragma unroll
        for (int d = 0; d < HDn/2; d++) acc[d] = fma2(ee, Vs[j][d], acc[d]);
    }
    float inv = 1.f / l;
    __nv_bfloat16* sprow = sp + ((size_t)g*Pn + tid)*512 + head*HDn;
    #pragma unroll
    for (int d = 0; d < HDn/2; d += 2) {
        float2 p0 = f2unpack(acc[d]);
        float2 p1 = f2unpack(acc[d+1]);
        __nv_bfloat162 h01, l01, h23, l23;
        split2(p0.x*inv, p0.y*inv, h01, l01);
        split2(p1.x*inv, p1.y*inv, h23, l23);
        *reinterpret_cast<__nv_bfloat162*>(sprow + 2*d)     = h01;
        *reinterpret_cast<__nv_bfloat162*>(sprow + 2*d + 2) = h23;
        *reinterpret_cast<__nv_bfloat162*>(sprow + 256 + 2*d)     = l01;
        *reinterpret_cast<__nv_bfloat162*>(sprow + 256 + 2*d + 2) = l23;
    }
}

// ---------------- LayerNorm(x + t)*g + b --------------------------------
template<bool WSPLIT>
__global__ void __launch_bounds__(Dn)
ln_kernel(const float* __restrict__ x, const float* __restrict__ t,
          const float* __restrict__ gam, const float* __restrict__ bet,
          float* __restrict__ out, __nv_bfloat16* __restrict__ sp)
{
    int row = blockIdx.x;
    int f   = threadIdx.x;
    size_t idx = (size_t)row*Dn + f;
    float v = x[idx] + t[idx];

    __shared__ float sh[8];
    int lane = f & 31, w = f >> 5;

    float s = v;
    #pragma unroll
    for (int off = 16; off > 0; off >>= 1) s += __shfl_xor_sync(0xffffffffu, s, off);
    if (lane == 0) sh[w] = s;
    __syncthreads();
    float mean = 0.f;
    #pragma unroll
    for (int i = 0; i < 8; i++) mean += sh[i];
    mean *= (1.f/Dn);

    float d  = v - mean;
    float s2 = d*d;
    #pragma unroll
    for (int off = 16; off > 0; off >>= 1) s2 += __shfl_xor_sync(0xffffffffu, s2, off);
    __syncthreads();
    if (lane == 0) sh[w] = s2;
    __syncthreads();
    float var = 0.f;
    #pragma unroll
    for (int i = 0; i < 8; i++) var += sh[i];
    var *= (1.f/Dn);

    float r = rsqrtf(var + 1e-5f);
    float o = d*r*gam[f] + bet[f];
    out[idx] = o;
    if (WSPLIT) {
        __nv_bfloat16 hb = __float2bfloat16_rn(o);
        __nv_bfloat16 lb = __float2bfloat16_rn(o - __bfloat162float(hb));
        sp[(size_t)row*512 + f]       = hb;
        sp[(size_t)row*512 + 256 + f] = lb;
    }
}

// ---------------------------------------------------------------------------
extern "C" void kernel_launch(void* const* d_in, const int* in_sizes, int n_in,
                              void* d_out, int out_size)
{
    const float* x    = (const float*)d_in[0];
    const int*   ei   = (const int*)  d_in[1];
    const float* c1W  = (const float*)d_in[6];
    const float* c1b  = (const float*)d_in[7];
    const float* c2W  = (const float*)d_in[8];
    const float* c2b  = (const float*)d_in[9];
    const float* WqA  = (const float*)d_in[10];
    const float* bqA  = (const float*)d_in[11];
    const float* WkA  = (const float*)d_in[12];
    const float* bkA  = (const float*)d_in[13];
    const float* WvA  = (const float*)d_in[14];
    const float* bvA  = (const float*)d_in[15];
    const float* WoA  = (const float*)d_in[16];
    const float* boA  = (const float*)d_in[17];
    const float* W1A  = (const float*)d_in[18];
    const float* b1A  = (const float*)d_in[19];
    const float* W2A  = (const float*)d_in[20];
    const float* b2A  = (const float*)d_in[21];
    const float* l1gA = (const float*)d_in[22];
    const float* l1bA = (const float*)d_in[23];
    const float* l2gA = (const float*)d_in[24];
    const float* l2bA = (const float*)d_in[25];
    float* out = (float*)d_out;

    float *h, *tmp, *qkv, *wv;
    __nv_bfloat16 *as1, *as2, *w2;
    int *rp, *ci;
    cudaGetSymbolAddress((void**)&h,    g_h);
    cudaGetSymbolAddress((void**)&tmp,  g_tmp);
    cudaGetSymbolAddress((void**)&qkv,  g_qkv);
    cudaGetSymbolAddress((void**)&as1,  g_as1);
    cudaGetSymbolAddress((void**)&as2,  g_as2);
    cudaGetSymbolAddress((void**)&w2,   g_w2);
    cudaGetSymbolAddress((void**)&rp,   g_rp);
    cudaGetSymbolAddress((void**)&ci,   g_ci);
    cudaGetSymbolAddress((void**)&wv,   g_wv);

    cudaFuncSetAttribute(gemm_tc<0,false,true ,false>, cudaFuncAttributeMaxDynamicSharedMemorySize, GEMM_SMEM);
    cudaFuncSetAttribute(gemm_tc<2,false,true ,false>, cudaFuncAttributeMaxDynamicSharedMemorySize, GEMM_SMEM);
    cudaFuncSetAttribute(gemm_tc<1,false,true ,false>, cudaFuncAttributeMaxDynamicSharedMemorySize, GEMM_SMEM);
    cudaFuncSetAttribute(gemm_tc<1,true ,false,true >, cudaFuncAttributeMaxDynamicSharedMemorySize, GEMM_SMEM);

    // ---- launch 0: graph setup ----
    k_setup<<<1, Pn>>>(ei, rp, ci, wv);

    // ---- launch 1: all weight packs ([N][2K] hi|lo) ----
    const long long oC1 = 0, oC2 = W2_CONV;
    const long long oL  = 2*W2_CONV;
    WPack wp;
    {
        int i = 0;
        long long s = 0;
        auto add = [&](const float* src, long long dst, int K, int N) {
            wp.d[i] = {src, dst, K, N};
            wp.start[i] = s;
            s += (long long)K*N;
            i++;
        };
        add(c1W, oC1, Dn, Dn);
        add(c2W, oC2, Dn, Dn);
        for (int l = 0; l < 2; l++) {
            long long b = oL + (long long)l*W2_LAYER;
            add(WqA + (size_t)l*65536,  b,             Dn, Dn);
            add(WkA + (size_t)l*65536,  b + W2_CONV,   Dn, Dn);
            add(WvA + (size_t)l*65536,  b + 2*W2_CONV, Dn, Dn);
            add(WoA + (size_t)l*65536,  b + 3*W2_CONV, Dn, Dn);
            add(W1A + (size_t)l*262144, b + 4*W2_CONV, Dn, DFn);
            add(W2A + (size_t)l*262144, b + 4*W2_CONV + W2_FFN, DFn, Dn);
        }
        wp.start[14] = s;
    }
    k_wprepAll<<<(int)((wp.start[14] + 255)/256), 256>>>(wp);

    // ---- launch 2: input split ----
    k_asplit<<<(Mn*64)/256, 256>>>(x, as1);

    dim3 gD(2, Mn/128);      // N=256 GEMMs, 1024 CTAs
    dim3 gQKV(6, Mn/128);    // N=768 fused QKV
    dim3 gF1(8, Mn/128);     // N=1024 FFN1

    // ---- launch 3 (profiled): GCN conv1 GEMM ----
    gemm_tc<0,false,true,false><<<gD, 256, GEMM_SMEM>>>(as1, 512, w2 + oC1, 512, nullptr, nullptr, nullptr, tmp, nullptr, Dn, Dn);
    agg_csr<false><<<Mn/8, 256>>>(tmp, rp, ci, wv, c1b, nullptr, as1);
    gemm_tc<0,false,true,false><<<gD, 256, GEMM_SMEM>>>(as1, 512, w2 + oC2, 512, nullptr, nullptr, nullptr, tmp, nullptr, Dn, Dn);
    agg_csr<true ><<<Mn/8, 256>>>(tmp, rp, ci, wv, c2b, h, as1);

    for (int l = 0; l < 2; l++) {
        long long b = oL + (long long)l*W2_LAYER;
        const float* bq = bqA + (size_t)l*Dn;
        const float* bk = bkA + (size_t)l*Dn;
        const float* bv = bvA + (size_t)l*Dn;
        const float* bo = boA + (size_t)l*Dn;
        const float* b1 = b1A + (size_t)l*DFn;
        const float* b2 = b2A + (size_t)l*Dn;
        const float* l1g = l1gA + (size_t)l*Dn; const float* l1b = l1bA + (size_t)l*Dn;
        const float* l2g = l2gA + (size_t)l*Dn; const float* l2b = l2bA + (size_t)l*Dn;

        gemm_tc<2,false,true,false><<<gQKV, 256, GEMM_SMEM>>>(as1, 512, w2 + b, 512, bq, bk, bv, qkv, nullptr, Dn, 768);

        attn_kernel<<<dim3(Hn, Gn), 128>>>(qkv, as1);

        gemm_tc<1,false,true,false><<<gD, 256, GEMM_SMEM>>>(as1, 512, w2 + b + 3*W2_CONV, 512, bo, nullptr, nullptr, tmp, nullptr, Dn, Dn);
        ln_kernel<true><<<Mn, Dn>>>(h, tmp, l1g, l1b, h, as1);

        gemm_tc<1,true,false,true><<<gF1, 256, GEMM_SMEM>>>(as1, 512, w2 + b + 4*W2_CONV, 512, b1, nullptr, nullptr, nullptr, as2, Dn, DFn);
        gemm_tc<1,false,true,false><<<gD, 256, GEMM_SMEM>>>(as2, 2048, w2 + b + 4*W2_CONV + W2_FFN, 2048, b2, nullptr, nullptr, tmp, nullptr, DFn, Dn);

        if (l == 0) ln_kernel<true ><<<Mn, Dn>>>(h, tmp, l2g, l2b, h, as1);
        else        ln_kernel<false><<<Mn, Dn>>>(h, tmp, l2g, l2b, out, nullptr);
    }
}

// round 13
// speedup vs baseline: 1.0575x; 1.0575x over previous
#include <cuda_runtime.h>
#include <cuda_bf16.h>
#include <mma.h>
#include <math.h>
#include <stdint.h>

using namespace nvcuda;

#define Gn 512
#define Pn 128
#define Dn 256
#define En 1024
#define Hn 8
#define HDn 32
#define DFn 1024
#define Mn (Gn*Pn)

typedef unsigned long long u64t;

// ---------------- scratch ----------------
__device__ float g_h[(size_t)Mn*Dn];
__device__ float g_tmp[(size_t)Mn*Dn];
__device__ float g_qkv[(size_t)Mn*3*Dn];
__device__ __nv_bfloat16 g_as1[(size_t)Mn*2*Dn];
__device__ __nv_bfloat16 g_as2[(size_t)Mn*2*DFn];

// packed weights: [N][2K] bf16 = hi | lo
#define W2_CONV   (Dn*2*Dn)
#define W2_FFN    (DFn*2*Dn)
#define W2_LAYER  (4*W2_CONV + 2*W2_FFN)
__device__ __nv_bfloat16 g_w2[2*W2_CONV + 2*W2_LAYER];

__device__ int   g_rp[Pn+1];
__device__ int   g_ci[En+Pn];
__device__ float g_wv[En+Pn];

// ---------------- helpers ----------------
__device__ __forceinline__ uint32_t smem_u32(const void* p) {
    uint32_t a;
    asm("{ .reg .u64 t; cvta.to.shared.u64 t, %1; cvt.u32.u64 %0, t; }" : "=r"(a) : "l"(p));
    return a;
}
__device__ __forceinline__ void cp_async16(uint32_t dst, const void* src) {
    asm volatile("cp.async.cg.shared.global [%0], [%1], 16;" :: "r"(dst), "l"(src) : "memory");
}
__device__ __forceinline__ void cp_commit() {
    asm volatile("cp.async.commit_group;" ::: "memory");
}
template<int N>
__device__ __forceinline__ void cp_wait() {
    asm volatile("cp.async.wait_group %0;" :: "n"(N) : "memory");
}
__device__ __forceinline__ u64t f2pack(float lo, float hi) {
    u64t r; asm("mov.b64 %0, {%1, %2};" : "=l"(r) : "f"(lo), "f"(hi)); return r;
}
__device__ __forceinline__ float2 f2unpack(u64t v) {
    float x, y; asm("mov.b64 {%0, %1}, %2;" : "=f"(x), "=f"(y) : "l"(v));
    return make_float2(x, y);
}
__device__ __forceinline__ u64t fma2(u64t a, u64t b, u64t c) {
    u64t d; asm("fma.rn.f32x2 %0, %1, %2, %3;" : "=l"(d) : "l"(a), "l"(b), "l"(c)); return d;
}
__device__ __forceinline__ void split2(float a, float b, __nv_bfloat162& hi, __nv_bfloat162& lo) {
    hi = __floats2bfloat162_rn(a, b);
    float2 f = __bfloat1622float2(hi);
    lo = __floats2bfloat162_rn(a - f.x, b - f.y);
}

// ---------------- fused graph setup (1 block) ----------------
__global__ void k_setup(const int* __restrict__ ei, int* rp, int* ci, float* wv) {
    __shared__ int   deg[Pn];
    __shared__ float dinv[Pn];
    __shared__ int   srp[Pn+1];
    __shared__ int   cur[Pn];
    int t = threadIdx.x;
    deg[t] = 1;
    __syncthreads();
    for (int e = t; e < En; e += Pn) atomicAdd(&deg[ei[En + e]], 1);
    __syncthreads();
    dinv[t] = rsqrtf((float)deg[t]);
    __syncthreads();
    if (t == 0) {
        int s = 0;
        for (int i = 0; i < Pn; i++) { srp[i] = s; cur[i] = s; s += deg[i]; }
        srp[Pn] = s;
    }
    __syncthreads();
    for (int e = t; e < En; e += Pn) {
        int s = ei[e], d = ei[En + e];
        int pos = atomicAdd(&cur[d], 1);
        ci[pos] = s; wv[pos] = dinv[s]*dinv[d];
    }
    {
        int pos = atomicAdd(&cur[t], 1);
        ci[pos] = t; wv[pos] = dinv[t]*dinv[t];
    }
    rp[t] = srp[t];
    if (t == 0) rp[Pn] = srp[Pn];
}

// ---------------- fused weight pack: W[K,N] fp32 -> [N][2K] hi|lo ----------
struct WD { const float* src; long long dst; int K; int N; };
struct WPack { WD d[14]; long long start[15]; };

__global__ void k_wprepAll(WPack p) {
    long long idx = (long long)blockIdx.x*256 + threadIdx.x;
    if (idx >= p.start[14]) return;
    int r = 0;
    #pragma unroll
    for (int i = 1; i < 14; i++) if (idx >= p.start[i]) r = i;
    long long local = idx - p.start[r];
    const WD d = p.d[r];
    int k = (int)(local / d.N), n = (int)(local - (long long)k*d.N);
    float a = d.src[local];
    __nv_bfloat16 h = __float2bfloat16_rn(a);
    __nv_bfloat16 l = __float2bfloat16_rn(a - __bfloat162float(h));
    __nv_bfloat16* O = g_w2 + d.dst + (size_t)n*2*d.K;
    O[k]       = h;
    O[d.K + k] = l;
}

// ---------------- input split ----------------
__global__ void k_asplit(const float* __restrict__ X, __nv_bfloat16* __restrict__ S) {
    int idx = blockIdx.x*blockDim.x + threadIdx.x;
    int row = idx >> 6;
    int g   = (idx & 63) * 4;
    float4 v = reinterpret_cast<const float4*>(X)[idx];
    __nv_bfloat162 h01, l01, h23, l23;
    split2(v.x, v.y, h01, l01);
    split2(v.z, v.w, h23, l23);
    __nv_bfloat16* hp = S + (size_t)row*512 + g;
    *reinterpret_cast<__nv_bfloat162*>(hp)     = h01;
    *reinterpret_cast<__nv_bfloat162*>(hp + 2) = h23;
    *reinterpret_cast<__nv_bfloat162*>(hp + 256)     = l01;
    *reinterpret_cast<__nv_bfloat162*>(hp + 256 + 2) = l23;
}

// ---------------- WMMA GEMM (R8 proven config) -------------------------------
#define ASTR 40
#define TILE_B 10240
#define STAGE_B (4*TILE_B)
#define GEMM_SMEM (2*STAGE_B)

template<int BMODE, bool RELU, bool WF32, bool WSPLIT>
__global__ void __launch_bounds__(256, 2)
gemm_tc(const __nv_bfloat16* __restrict__ A2, long long lda,
        const __nv_bfloat16* __restrict__ B2, long long ldb,
        const float* __restrict__ b0, const float* __restrict__ b1p,
        const float* __restrict__ b2p,
        float* __restrict__ C, __nv_bfloat16* __restrict__ Csp,
        int K, int Ntot)
{
    extern __shared__ __align__(128) char dsm[];
    const int tid = threadIdx.x;
    const int wid = tid >> 5;
    const int wm = wid & 1;
    const int wn = wid >> 1;
    const int m0 = blockIdx.y * 128;
    const int n0 = blockIdx.x * 128;
    uint32_t sbase = smem_u32(dsm);

    const int nc = K >> 5;

    wmma::fragment<wmma::accumulator, 16,16,16, float> acc[4][2];
    #pragma unroll
    for (int i = 0; i < 4; i++)
        #pragma unroll
        for (int j = 0; j < 2; j++) wmma::fill_fragment(acc[i][j], 0.f);

    auto load_chunk = [&](int c, int stage) {
        int k0 = c << 5;
        uint32_t base = sbase + stage*STAGE_B;
        #pragma unroll
        for (int r = 0; r < 2; r++) {
            int id = tid + r*256;
            int row = id >> 2, seg = id & 3;
            const __nv_bfloat16* arow = A2 + (size_t)(m0+row)*lda + seg*8;
            const __nv_bfloat16* brow = B2 + (size_t)(n0+row)*ldb + seg*8;
            uint32_t soff = row*80 + seg*16;
            cp_async16(base + soff,            arow + k0);
            cp_async16(base + TILE_B + soff,   arow + K + k0);
            cp_async16(base + 2*TILE_B + soff, brow + k0);
            cp_async16(base + 3*TILE_B + soff, brow + K + k0);
        }
        cp_commit();
    };

    load_chunk(0, 0);

    for (int c = 0; c < nc; c++) {
        const int stage = c & 1;
        cp_wait<0>();
        __syncthreads();
        if (c + 1 < nc) load_chunk(c+1, stage^1);

        const __nv_bfloat16* Ah = reinterpret_cast<const __nv_bfloat16*>(dsm + stage*STAGE_B);
        const __nv_bfloat16* Al = Ah + 5120;
        const __nv_bfloat16* Bh = Ah + 10240;
        const __nv_bfloat16* Bl = Ah + 15360;

        #pragma unroll
        for (int ks = 0; ks < 2; ks++) {
            wmma::fragment<wmma::matrix_b, 16,16,16, __nv_bfloat16, wmma::col_major> bh[2], bl[2];
            #pragma unroll
            for (int nt = 0; nt < 2; nt++) {
                wmma::load_matrix_sync(bh[nt], Bh + (wn*32 + nt*16)*ASTR + ks*16, ASTR);
                wmma::load_matrix_sync(bl[nt], Bl + (wn*32 + nt*16)*ASTR + ks*16, ASTR);
            }
            {
                wmma::fragment<wmma::matrix_a, 16,16,16, __nv_bfloat16, wmma::row_major> af[4];
                #pragma unroll
                for (int mt = 0; mt < 4; mt++)
                    wmma::load_matrix_sync(af[mt], Ah + (wm*64 + mt*16)*ASTR + ks*16, ASTR);
                #pragma unroll
                for (int mt = 0; mt < 4; mt++)
                    #pragma unroll
                    for (int nt = 0; nt < 2; nt++)
                        wmma::mma_sync(acc[mt][nt], af[mt], bh[nt], acc[mt][nt]);
                #pragma unroll
                for (int mt = 0; mt < 4; mt++)
                    #pragma unroll
                    for (int nt = 0; nt < 2; nt++)
                        wmma::mma_sync(acc[mt][nt], af[mt], bl[nt], acc[mt][nt]);
            }
            {
                wmma::fragment<wmma::matrix_a, 16,16,16, __nv_bfloat16, wmma::row_major> af[4];
                #pragma unroll
                for (int mt = 0; mt < 4; mt++)
                    wmma::load_matrix_sync(af[mt], Al + (wm*64 + mt*16)*ASTR + ks*16, ASTR);
                #pragma unroll
                for (int mt = 0; mt < 4; mt++)
                    #pragma unroll
                    for (int nt = 0; nt < 2; nt++)
                        wmma::mma_sync(acc[mt][nt], af[mt], bh[nt], acc[mt][nt]);
            }
        }
    }
    __syncthreads();

    const float* bp = nullptr;
    int bbase = 0;
    if (BMODE == 1) { bp = b0; bbase = n0; }
    if (BMODE == 2) {
        int sel = blockIdx.x >> 1;
        bp = (sel == 0) ? b0 : ((sel == 1) ? b1p : b2p);
        bbase = (blockIdx.x & 1) * 128;
    }

    float* stg = reinterpret_cast<float*>(dsm);
    #pragma unroll
    for (int mt = 0; mt < 4; mt++)
        #pragma unroll
        for (int nt = 0; nt < 2; nt++)
            wmma::store_matrix_sync(stg + (wm*64 + mt*16)*136 + wn*32 + nt*16,
                                    acc[mt][nt], 136, wmma::mem_row_major);
    __syncthreads();

    int row = tid >> 1;
    int cb  = (tid & 1) * 64;
    const float* sr = stg + row*136 + cb;
    size_t crow  = (size_t)(m0+row)*Ntot + n0 + cb;
    size_t shrow = (size_t)(m0+row)*(2*(size_t)Ntot) + n0 + cb;
    #pragma unroll
    for (int j = 0; j < 64; j += 4) {
        float4 v = *reinterpret_cast<const float4*>(sr + j);
        if (BMODE) {
            float4 b = *reinterpret_cast<const float4*>(bp + bbase + cb + j);
            v.x += b.x; v.y += b.y; v.z += b.z; v.w += b.w;
        }
        if (RELU) {
            v.x = fmaxf(v.x, 0.f); v.y = fmaxf(v.y, 0.f);
            v.z = fmaxf(v.z, 0.f); v.w = fmaxf(v.w, 0.f);
        }
        if (WF32) *reinterpret_cast<float4*>(C + crow + j) = v;
        if (WSPLIT) {
            __nv_bfloat162 h01, l01, h23, l23;
            split2(v.x, v.y, h01, l01);
            split2(v.z, v.w, h23, l23);
            __nv_bfloat16* hp = Csp + shrow + j;
            *reinterpret_cast<__nv_bfloat162*>(hp)     = h01;
            *reinterpret_cast<__nv_bfloat162*>(hp + 2) = h23;
            *reinterpret_cast<__nv_bfloat162*>(hp + Ntot)     = l01;
            *reinterpret_cast<__nv_bfloat162*>(hp + Ntot + 2) = l23;
        }
    }
}

// ---------------- EXPERIMENT: BN=64, 32x32 warp tile, 3 CTAs/SM -------------
// acc 32 regs/thread -> launch_bounds(256,3). fp32 out only (used for conv2).
#define STAGE64 30720     // Ah 10240 | Al 10240 | Bh 5120 | Bl 5120
#define GEMM64_SMEM (2*STAGE64)   // 61440 >= epilogue 128*68*4 = 34816

__global__ void __launch_bounds__(256, 3)
gemm64(const __nv_bfloat16* __restrict__ A2, long long lda,
       const __nv_bfloat16* __restrict__ B2, long long ldb,
       float* __restrict__ C, int K, int Ntot)
{
    extern __shared__ __align__(128) char dsm[];
    const int tid = threadIdx.x;
    const int wid = tid >> 5;
    const int wm = wid & 3;       // 0..3  (32-row slice)
    const int wn = wid >> 2;      // 0..1  (32-col slice)
    const int m0 = blockIdx.y * 128;
    const int n0 = blockIdx.x * 64;
    uint32_t sbase = smem_u32(dsm);

    const int nc = K >> 5;

    wmma::fragment<wmma::accumulator, 16,16,16, float> acc[2][2];
    #pragma unroll
    for (int i = 0; i < 2; i++)
        #pragma unroll
        for (int j = 0; j < 2; j++) wmma::fill_fragment(acc[i][j], 0.f);

    auto load_chunk = [&](int c, int stage) {
        int k0 = c << 5;
        uint32_t base = sbase + stage*STAGE64;
        #pragma unroll
        for (int r = 0; r < 2; r++) {
            int id = tid + r*256;
            int row = id >> 2, seg = id & 3;
            const __nv_bfloat16* arow = A2 + (size_t)(m0+row)*lda + seg*8;
            uint32_t soff = row*80 + seg*16;
            cp_async16(base + soff,         arow + k0);       // A hi
            cp_async16(base + 10240 + soff, arow + K + k0);   // A lo
        }
        {
            int row = tid >> 2, seg = tid & 3;   // row 0..63
            const __nv_bfloat16* brow = B2 + (size_t)(n0+row)*ldb + seg*8;
            uint32_t soff = row*80 + seg*16;
            cp_async16(base + 20480 + soff, brow + k0);       // B hi
            cp_async16(base + 25600 + soff, brow + K + k0);   // B lo
        }
        cp_commit();
    };

    load_chunk(0, 0);

    for (int c = 0; c < nc; c++) {
        const int stage = c & 1;
        cp_wait<0>();
        __syncthreads();
        if (c + 1 < nc) load_chunk(c+1, stage^1);

        const __nv_bfloat16* Ah = reinterpret_cast<const __nv_bfloat16*>(dsm + stage*STAGE64);
        const __nv_bfloat16* Al = Ah + 5120;
        const __nv_bfloat16* Bh = Ah + 10240;
        const __nv_bfloat16* Bl = Ah + 12800;

        #pragma unroll
        for (int ks = 0; ks < 2; ks++) {
            wmma::fragment<wmma::matrix_b, 16,16,16, __nv_bfloat16, wmma::col_major> bh[2], bl[2];
            #pragma unroll
            for (int nt = 0; nt < 2; nt++) {
                wmma::load_matrix_sync(bh[nt], Bh + (wn*32 + nt*16)*ASTR + ks*16, ASTR);
                wmma::load_matrix_sync(bl[nt], Bl + (wn*32 + nt*16)*ASTR + ks*16, ASTR);
            }
            {
                wmma::fragment<wmma::matrix_a, 16,16,16, __nv_bfloat16, wmma::row_major> af[2];
                #pragma unroll
                for (int mt = 0; mt < 2; mt++)
                    wmma::load_matrix_sync(af[mt], Ah + (wm*32 + mt*16)*ASTR + ks*16, ASTR);
                #pragma unroll
                for (int mt = 0; mt < 2; mt++)
                    #pragma unroll
                    for (int nt = 0; nt < 2; nt++)
                        wmma::mma_sync(acc[mt][nt], af[mt], bh[nt], acc[mt][nt]);
                #pragma unroll
                for (int mt = 0; mt < 2; mt++)
                    #pragma unroll
                    for (int nt = 0; nt < 2; nt++)
                        wmma::mma_sync(acc[mt][nt], af[mt], bl[nt], acc[mt][nt]);
            }
            {
                wmma::fragment<wmma::matrix_a, 16,16,16, __nv_bfloat16, wmma::row_major> af[2];
                #pragma unroll
                for (int mt = 0; mt < 2; mt++)
                    wmma::load_matrix_sync(af[mt], Al + (wm*32 + mt*16)*ASTR + ks*16, ASTR);
                #pragma unroll
                for (int mt = 0; mt < 2; mt++)
                    #pragma unroll
                    for (int nt = 0; nt < 2; nt++)
                        wmma::mma_sync(acc[mt][nt], af[mt], bh[nt], acc[mt][nt]);
            }
        }
    }
    __syncthreads();

    // epilogue: stage stride 68 floats
    float* stg = reinterpret_cast<float*>(dsm);
    #pragma unroll
    for (int mt = 0; mt < 2; mt++)
        #pragma unroll
        for (int nt = 0; nt < 2; nt++)
            wmma::store_matrix_sync(stg + (wm*32 + mt*16)*68 + wn*32 + nt*16,
                                    acc[mt][nt], 68, wmma::mem_row_major);
    __syncthreads();

    int row = tid >> 1;
    int cb  = (tid & 1) * 32;
    const float* sr = stg + row*68 + cb;
    float* dst = C + (size_t)(m0+row)*Ntot + n0 + cb;
    #pragma unroll
    for (int j = 0; j < 32; j += 4)
        *reinterpret_cast<float4*>(dst + j) = *reinterpret_cast<const float4*>(sr + j);
}

// ---------------- sparse GCN aggregation (+bias +relu) ----------------------
template<bool WF32>
__global__ void __launch_bounds__(256)
agg_csr(const float* __restrict__ xw, const int* __restrict__ rp,
        const int* __restrict__ ci, const float* __restrict__ wv,
        const float* __restrict__ bias, float* __restrict__ outf,
        __nv_bfloat16* __restrict__ sp)
{
    int warp = blockIdx.x*8 + (threadIdx.x >> 5);
    int lane = threadIdx.x & 31;
    int p = warp & 127;
    size_t gbase = (size_t)(warp & ~127) * Dn;

    float4 a0 = make_float4(0.f,0.f,0.f,0.f);
    float4 a1 = make_float4(0.f,0.f,0.f,0.f);
    int s0 = rp[p], s1 = rp[p+1];
    for (int e = s0; e < s1; e++) {
        int src = ci[e]; float w = wv[e];
        const float4* rowp = reinterpret_cast<const float4*>(xw + gbase + (size_t)src*Dn);
        float4 x0 = rowp[lane];
        float4 x1 = rowp[lane+32];
        a0.x = fmaf(w, x0.x, a0.x); a0.y = fmaf(w, x0.y, a0.y);
        a0.z = fmaf(w, x0.z, a0.z); a0.w = fmaf(w, x0.w, a0.w);
        a1.x = fmaf(w, x1.x, a1.x); a1.y = fmaf(w, x1.y, a1.y);
        a1.z = fmaf(w, x1.z, a1.z); a1.w = fmaf(w, x1.w, a1.w);
    }
    int c0 = lane*4;
    float4 b0 = *reinterpret_cast<const float4*>(bias + c0);
    float4 b1 = *reinterpret_cast<const float4*>(bias + c0 + 128);
    a0.x = fmaxf(a0.x + b0.x, 0.f); a0.y = fmaxf(a0.y + b0.y, 0.f);
    a0.z = fmaxf(a0.z + b0.z, 0.f); a0.w = fmaxf(a0.w + b0.w, 0.f);
    a1.x = fmaxf(a1.x + b1.x, 0.f); a1.y = fmaxf(a1.y + b1.y, 0.f);
    a1.z = fmaxf(a1.z + b1.z, 0.f); a1.w = fmaxf(a1.w + b1.w, 0.f);

    if (WF32) {
        float* dst = outf + (size_t)warp*Dn;
        *reinterpret_cast<float4*>(dst + c0)       = a0;
        *reinterpret_cast<float4*>(dst + c0 + 128) = a1;
    }
    __nv_bfloat16* sprow = sp + (size_t)warp*512;
    __nv_bfloat162 h01, l01, h23, l23;
    split2(a0.x, a0.y, h01, l01); split2(a0.z, a0.w, h23, l23);
    *reinterpret_cast<__nv_bfloat162*>(sprow + c0)     = h01;
    *reinterpret_cast<__nv_bfloat162*>(sprow + c0 + 2) = h23;
    *reinterpret_cast<__nv_bfloat162*>(sprow + 256 + c0)     = l01;
    *reinterpret_cast<__nv_bfloat162*>(sprow + 256 + c0 + 2) = l23;
    split2(a1.x, a1.y, h01, l01); split2(a1.z, a1.w, h23, l23);
    *reinterpret_cast<__nv_bfloat162*>(sprow + c0 + 128)     = h01;
    *reinterpret_cast<__nv_bfloat162*>(sprow + c0 + 130)     = h23;
    *reinterpret_cast<__nv_bfloat162*>(sprow + 256 + c0 + 128) = l01;
    *reinterpret_cast<__nv_bfloat162*>(sprow + 256 + c0 + 130) = l23;
}

// ---------------- attention ----------------
__global__ void __launch_bounds__(128)
attn_kernel(const float* __restrict__ qkv, __nv_bfloat16* __restrict__ sp)
{
    int head = blockIdx.x;
    int g    = blockIdx.y;
    int tid  = threadIdx.x;

    __shared__ u64t Ks[Pn][HDn/2];
    __shared__ u64t Vs[Pn][HDn/2];

    size_t base = ((size_t)g*Pn + tid)*768 + head*HDn;
    u64t qr[HDn/2];
    #pragma unroll
    for (int j = 0; j < HDn/4; j++) {
        float4 qv = reinterpret_cast<const float4*>(qkv + base)[j];
        float4 kv = reinterpret_cast<const float4*>(qkv + base + 256)[j];
        float4 vv = reinterpret_cast<const float4*>(qkv + base + 512)[j];
        qr[2*j]   = f2pack(qv.x, qv.y);
        qr[2*j+1] = f2pack(qv.z, qv.w);
        Ks[tid][2*j]   = f2pack(kv.x, kv.y);
        Ks[tid][2*j+1] = f2pack(kv.z, kv.w);
        Vs[tid][2*j]   = f2pack(vv.x, vv.y);
        Vs[tid][2*j+1] = f2pack(vv.z, vv.w);
    }
    __syncthreads();

    const float scale = 0.17677669529663687f;
    float l = 0.f;
    u64t acc[HDn/2];
    #pragma unroll
    for (int d = 0; d < HDn/2; d++) acc[d] = 0ull;

    for (int j = 0; j < Pn; j++) {
        u64t s2 = 0ull;
        #pragma unroll
        for (int d = 0; d < HDn/2; d++) s2 = fma2(qr[d], Ks[j][d], s2);
        float2 sv = f2unpack(s2);
        float e = __expf((sv.x + sv.y)*scale);
        l += e;
        u64t ee = f2pack(e, e);
        #pragma unroll
        for (int d = 0; d < HDn/2; d++) acc[d] = fma2(ee, Vs[j][d], acc[d]);
    }
    float inv = 1.f / l;
    __nv_bfloat16* sprow = sp + ((size_t)g*Pn + tid)*512 + head*HDn;
    #pragma unroll
    for (int d = 0; d < HDn/2; d += 2) {
        float2 p0 = f2unpack(acc[d]);
        float2 p1 = f2unpack(acc[d+1]);
        __nv_bfloat162 h01, l01, h23, l23;
        split2(p0.x*inv, p0.y*inv, h01, l01);
        split2(p1.x*inv, p1.y*inv, h23, l23);
        *reinterpret_cast<__nv_bfloat162*>(sprow + 2*d)     = h01;
        *reinterpret_cast<__nv_bfloat162*>(sprow + 2*d + 2) = h23;
        *reinterpret_cast<__nv_bfloat162*>(sprow + 256 + 2*d)     = l01;
        *reinterpret_cast<__nv_bfloat162*>(sprow + 256 + 2*d + 2) = l23;
    }
}

// ---------------- LayerNorm(x + t)*g + b ; 2 rows per CTA -------------------
template<bool WSPLIT>
__global__ void __launch_bounds__(512)
ln_kernel(const float* __restrict__ x, const float* __restrict__ t,
          const float* __restrict__ gam, const float* __restrict__ bet,
          float* __restrict__ out, __nv_bfloat16* __restrict__ sp)
{
    int grp = threadIdx.x >> 8;        // 0..1
    int f   = threadIdx.x & 255;
    int row = blockIdx.x*2 + grp;
    size_t idx = (size_t)row*Dn + f;
    float v = x[idx] + t[idx];

    __shared__ float sh[16];
    int lane = threadIdx.x & 31, w = threadIdx.x >> 5;   // w 0..15; group0 = w 0..7

    float s = v;
    #pragma unroll
    for (int off = 16; off > 0; off >>= 1) s += __shfl_xor_sync(0xffffffffu, s, off);
    if (lane == 0) sh[w] = s;
    __syncthreads();
    float mean = 0.f;
    #pragma unroll
    for (int i = 0; i < 8; i++) mean += sh[grp*8 + i];
    mean *= (1.f/Dn);

    float d  = v - mean;
    float s2 = d*d;
    #pragma unroll
    for (int off = 16; off > 0; off >>= 1) s2 += __shfl_xor_sync(0xffffffffu, s2, off);
    __syncthreads();
    if (lane == 0) sh[w] = s2;
    __syncthreads();
    float var = 0.f;
    #pragma unroll
    for (int i = 0; i < 8; i++) var += sh[grp*8 + i];
    var *= (1.f/Dn);

    float r = rsqrtf(var + 1e-5f);
    float o = d*r*gam[f] + bet[f];
    out[idx] = o;
    if (WSPLIT) {
        __nv_bfloat16 hb = __float2bfloat16_rn(o);
        __nv_bfloat16 lb = __float2bfloat16_rn(o - __bfloat162float(hb));
        sp[(size_t)row*512 + f]       = hb;
        sp[(size_t)row*512 + 256 + f] = lb;
    }
}

// ---------------------------------------------------------------------------
extern "C" void kernel_launch(void* const* d_in, const int* in_sizes, int n_in,
                              void* d_out, int out_size)
{
    const float* x    = (const float*)d_in[0];
    const int*   ei   = (const int*)  d_in[1];
    const float* c1W  = (const float*)d_in[6];
    const float* c1b  = (const float*)d_in[7];
    const float* c2W  = (const float*)d_in[8];
    const float* c2b  = (const float*)d_in[9];
    const float* WqA  = (const float*)d_in[10];
    const float* bqA  = (const float*)d_in[11];
    const float* WkA  = (const float*)d_in[12];
    const float* bkA  = (const float*)d_in[13];
    const float* WvA  = (const float*)d_in[14];
    const float* bvA  = (const float*)d_in[15];
    const float* WoA  = (const float*)d_in[16];
    const float* boA  = (const float*)d_in[17];
    const float* W1A  = (const float*)d_in[18];
    const float* b1A  = (const float*)d_in[19];
    const float* W2A  = (const float*)d_in[20];
    const float* b2A  = (const float*)d_in[21];
    const float* l1gA = (const float*)d_in[22];
    const float* l1bA = (const float*)d_in[23];
    const float* l2gA = (const float*)d_in[24];
    const float* l2bA = (const float*)d_in[25];
    float* out = (float*)d_out;

    float *h, *tmp, *qkv, *wv;
    __nv_bfloat16 *as1, *as2, *w2;
    int *rp, *ci;
    cudaGetSymbolAddress((void**)&h,    g_h);
    cudaGetSymbolAddress((void**)&tmp,  g_tmp);
    cudaGetSymbolAddress((void**)&qkv,  g_qkv);
    cudaGetSymbolAddress((void**)&as1,  g_as1);
    cudaGetSymbolAddress((void**)&as2,  g_as2);
    cudaGetSymbolAddress((void**)&w2,   g_w2);
    cudaGetSymbolAddress((void**)&rp,   g_rp);
    cudaGetSymbolAddress((void**)&ci,   g_ci);
    cudaGetSymbolAddress((void**)&wv,   g_wv);

    cudaFuncSetAttribute(gemm_tc<0,false,true ,false>, cudaFuncAttributeMaxDynamicSharedMemorySize, GEMM_SMEM);
    cudaFuncSetAttribute(gemm_tc<2,false,true ,false>, cudaFuncAttributeMaxDynamicSharedMemorySize, GEMM_SMEM);
    cudaFuncSetAttribute(gemm_tc<1,false,true ,false>, cudaFuncAttributeMaxDynamicSharedMemorySize, GEMM_SMEM);
    cudaFuncSetAttribute(gemm_tc<1,true ,false,true >, cudaFuncAttributeMaxDynamicSharedMemorySize, GEMM_SMEM);
    cudaFuncSetAttribute(gemm64, cudaFuncAttributeMaxDynamicSharedMemorySize, GEMM64_SMEM);

    // ---- launch 0: graph setup ----
    k_setup<<<1, Pn>>>(ei, rp, ci, wv);

    // ---- launch 1: all weight packs ----
    const long long oC1 = 0, oC2 = W2_CONV;
    const long long oL  = 2*W2_CONV;
    WPack wp;
    {
        int i = 0;
        long long s = 0;
        auto add = [&](const float* src, long long dst, int K, int N) {
            wp.d[i] = {src, dst, K, N};
            wp.start[i] = s;
            s += (long long)K*N;
            i++;
        };
        add(c1W, oC1, Dn, Dn);
        add(c2W, oC2, Dn, Dn);
        for (int l = 0; l < 2; l++) {
            long long b = oL + (long long)l*W2_LAYER;
            add(WqA + (size_t)l*65536,  b,             Dn, Dn);
            add(WkA + (size_t)l*65536,  b + W2_CONV,   Dn, Dn);
            add(WvA + (size_t)l*65536,  b + 2*W2_CONV, Dn, Dn);
            add(WoA + (size_t)l*65536,  b + 3*W2_CONV, Dn, Dn);
            add(W1A + (size_t)l*262144, b + 4*W2_CONV, Dn, DFn);
            add(W2A + (size_t)l*262144, b + 4*W2_CONV + W2_FFN, DFn, Dn);
        }
        wp.start[14] = s;
    }
    k_wprepAll<<<(int)((wp.start[14] + 255)/256), 256>>>(wp);

    // ---- launch 2: input split ----
    k_asplit<<<(Mn*64)/256, 256>>>(x, as1);

    dim3 gD(2, Mn/128);
    dim3 g64(Dn/64, Mn/128);   // (4, 512) experiment grid
    dim3 gQKV(6, Mn/128);
    dim3 gF1(8, Mn/128);

    // ---- conv1 (R8 config) + agg ----
    gemm_tc<0,false,true,false><<<gD, 256, GEMM_SMEM>>>(as1, 512, w2 + oC1, 512, nullptr, nullptr, nullptr, tmp, nullptr, Dn, Dn);
    agg_csr<false><<<Mn/8, 256>>>(tmp, rp, ci, wv, c1b, nullptr, as1);
    // ---- conv2: EXPERIMENT gemm64 (profiled slot, launch idx 5) ----
    gemm64<<<g64, 256, GEMM64_SMEM>>>(as1, 512, w2 + oC2, 512, tmp, Dn, Dn);
    agg_csr<true ><<<Mn/8, 256>>>(tmp, rp, ci, wv, c2b, h, as1);

    for (int l = 0; l < 2; l++) {
        long long b = oL + (long long)l*W2_LAYER;
        const float* bq = bqA + (size_t)l*Dn;
        const float* bk = bkA + (size_t)l*Dn;
        const float* bv = bvA + (size_t)l*Dn;
        const float* bo = boA + (size_t)l*Dn;
        const float* b1 = b1A + (size_t)l*DFn;
        const float* b2 = b2A + (size_t)l*Dn;
        const float* l1g = l1gA + (size_t)l*Dn; const float* l1b = l1bA + (size_t)l*Dn;
        const float* l2g = l2gA + (size_t)l*Dn; const float* l2b = l2bA + (size_t)l*Dn;

        gemm_tc<2,false,true,false><<<gQKV, 256, GEMM_SMEM>>>(as1, 512, w2 + b, 512, bq, bk, bv, qkv, nullptr, Dn, 768);

        attn_kernel<<<dim3(Hn, Gn), 128>>>(qkv, as1);

        gemm_tc<1,false,true,false><<<gD, 256, GEMM_SMEM>>>(as1, 512, w2 + b + 3*W2_CONV, 512, bo, nullptr, nullptr, tmp, nullptr, Dn, Dn);
        ln_kernel<true><<<Mn/2, 512>>>(h, tmp, l1g, l1b, h, as1);

        gemm_tc<1,true,false,true><<<gF1, 256, GEMM_SMEM>>>(as1, 512, w2 + b + 4*W2_CONV, 512, b1, nullptr, nullptr, nullptr, as2, Dn, DFn);
        gemm_tc<1,false,true,false><<<gD, 256, GEMM_SMEM>>>(as2, 2048, w2 + b + 4*W2_CONV + W2_FFN, 2048, b2, nullptr, nullptr, tmp, nullptr, DFn, Dn);

        if (l == 0) ln_kernel<true ><<<Mn/2, 512>>>(h, tmp, l2g, l2b, h, as1);
        else        ln_kernel<false><<<Mn/2, 512>>>(h, tmp, l2g, l2b, out, nullptr);
    }
}

// round 14
// speedup vs baseline: 1.8592x; 1.7581x over previous
#include <cuda_runtime.h>
#include <cuda_fp16.h>
#include <mma.h>
#include <math.h>
#include <stdint.h>

using namespace nvcuda;

#define Gn 512
#define Pn 128
#define Dn 256
#define En 1024
#define Hn 8
#define HDn 32
#define DFn 1024
#define Mn (Gn*Pn)

typedef unsigned long long u64t;

// ---------------- scratch ----------------
__device__ float  g_h[(size_t)Mn*Dn];
__device__ float  g_tmp[(size_t)Mn*Dn];
__device__ float  g_qkv[(size_t)Mn*3*Dn];
__device__ __half g_x16[(size_t)Mn*Dn];
__device__ __half g_a16[(size_t)Mn*Dn];
__device__ __half g_f16[(size_t)Mn*DFn];

// packed weights: [N][K] fp16
#define W16_CONV  (Dn*Dn)                    // 65536
#define W16_FFN   (DFn*Dn)                   // 262144
#define W16_LAYER (4*W16_CONV + 2*W16_FFN)   // 786432
__device__ __half g_w16[2*W16_CONV + 2*W16_LAYER];

__device__ int   g_rp[Pn+1];
__device__ int   g_ci[En+Pn];
__device__ float g_wv[En+Pn];

// ---------------- helpers ----------------
__device__ __forceinline__ uint32_t smem_u32(const void* p) {
    uint32_t a;
    asm("{ .reg .u64 t; cvta.to.shared.u64 t, %1; cvt.u32.u64 %0, t; }" : "=r"(a) : "l"(p));
    return a;
}
__device__ __forceinline__ void cp_async16(uint32_t dst, const void* src) {
    asm volatile("cp.async.cg.shared.global [%0], [%1], 16;" :: "r"(dst), "l"(src) : "memory");
}
__device__ __forceinline__ void cp_commit() {
    asm volatile("cp.async.commit_group;" ::: "memory");
}
template<int N>
__device__ __forceinline__ void cp_wait() {
    asm volatile("cp.async.wait_group %0;" :: "n"(N) : "memory");
}
__device__ __forceinline__ u64t f2pack(float lo, float hi) {
    u64t r; asm("mov.b64 %0, {%1, %2};" : "=l"(r) : "f"(lo), "f"(hi)); return r;
}
__device__ __forceinline__ float2 f2unpack(u64t v) {
    float x, y; asm("mov.b64 {%0, %1}, %2;" : "=f"(x), "=f"(y) : "l"(v));
    return make_float2(x, y);
}
__device__ __forceinline__ u64t fma2(u64t a, u64t b, u64t c) {
    u64t d; asm("fma.rn.f32x2 %0, %1, %2, %3;" : "=l"(d) : "l"(a), "l"(b), "l"(c)); return d;
}

// ---------------- fused graph setup (1 block) ----------------
__global__ void k_setup(const int* __restrict__ ei, int* rp, int* ci, float* wv) {
    __shared__ int   deg[Pn];
    __shared__ float dinv[Pn];
    __shared__ int   srp[Pn+1];
    __shared__ int   cur[Pn];
    int t = threadIdx.x;
    deg[t] = 1;
    __syncthreads();
    for (int e = t; e < En; e += Pn) atomicAdd(&deg[ei[En + e]], 1);
    __syncthreads();
    dinv[t] = rsqrtf((float)deg[t]);
    __syncthreads();
    if (t == 0) {
        int s = 0;
        for (int i = 0; i < Pn; i++) { srp[i] = s; cur[i] = s; s += deg[i]; }
        srp[Pn] = s;
    }
    __syncthreads();
    for (int e = t; e < En; e += Pn) {
        int s = ei[e], d = ei[En + e];
        int pos = atomicAdd(&cur[d], 1);
        ci[pos] = s; wv[pos] = dinv[s]*dinv[d];
    }
    {
        int pos = atomicAdd(&cur[t], 1);
        ci[pos] = t; wv[pos] = dinv[t]*dinv[t];
    }
    rp[t] = srp[t];
    if (t == 0) rp[Pn] = srp[Pn];
}

// ---------------- fused weight pack: W[K,N] fp32 -> [N][K] fp16 -------------
struct WD { const float* src; long long dst; int K; int N; };
struct WPack { WD d[14]; long long start[15]; };

__global__ void k_wprepAll(WPack p) {
    long long idx = (long long)blockIdx.x*256 + threadIdx.x;
    if (idx >= p.start[14]) return;
    int r = 0;
    #pragma unroll
    for (int i = 1; i < 14; i++) if (idx >= p.start[i]) r = i;
    long long local = idx - p.start[r];
    const WD d = p.d[r];
    int k = (int)(local / d.N), n = (int)(local - (long long)k*d.N);
    g_w16[d.dst + (size_t)n*d.K + k] = __float2half_rn(d.src[local]);
}

// ---------------- input convert: X[M,256] fp32 -> fp16 ----------------------
__global__ void k_acvt(const float* __restrict__ X, __half* __restrict__ S) {
    int idx = blockIdx.x*blockDim.x + threadIdx.x;   // per 4 elems
    float4 v = reinterpret_cast<const float4*>(X)[idx];
    __half2 a = __floats2half2_rn(v.x, v.y);
    __half2 b = __floats2half2_rn(v.z, v.w);
    *reinterpret_cast<__half2*>(S + (size_t)idx*4)     = a;
    *reinterpret_cast<__half2*>(S + (size_t)idx*4 + 2) = b;
}

// ---------------- fp16 WMMA GEMM, BM=BN=128, BK=64, 2-stage ------------------
// A: [M][lda] fp16 ; B: [N][ldb] fp16 (k-contiguous rows).
// BMODE: 0 none, 1 single bias, 2 per-128col bias (QKV).
#define TSTR 72                    // halves (pitch 144B: 16B-aligned, ldsm conflict-free)
#define TILE16 18432               // 128*144 bytes
#define STAGE16 (2*TILE16)         // 36864
#define GEMM16_SMEM (2*STAGE16)    // 73728 >= epilogue 128*136*4 = 69632

template<int BMODE, bool RELU, bool WF32, bool WHALF>
__global__ void __launch_bounds__(256, 2)
gemm16(const __half* __restrict__ A, long long lda,
       const __half* __restrict__ B, long long ldb,
       const float* __restrict__ b0, const float* __restrict__ b1p,
       const float* __restrict__ b2p,
       float* __restrict__ C, __half* __restrict__ Ch,
       int K, int Ntot)
{
    extern __shared__ __align__(128) char dsm[];
    const int tid = threadIdx.x;
    const int wid = tid >> 5;
    const int wm = wid & 1;
    const int wn = wid >> 1;
    const int m0 = blockIdx.y * 128;
    const int n0 = blockIdx.x * 128;
    uint32_t sbase = smem_u32(dsm);

    const int nc = K >> 6;

    wmma::fragment<wmma::accumulator, 16,16,16, float> acc[4][2];
    #pragma unroll
    for (int i = 0; i < 4; i++)
        #pragma unroll
        for (int j = 0; j < 2; j++) wmma::fill_fragment(acc[i][j], 0.f);

    auto load_chunk = [&](int c, int stage) {
        int k0 = c << 6;
        uint32_t baseA = sbase + stage*STAGE16;
        uint32_t baseB = baseA + TILE16;
        #pragma unroll
        for (int r = 0; r < 4; r++) {
            int id = tid + r*256;          // 0..1023
            int row = id >> 3, seg = id & 7;
            uint32_t soff = row*144 + seg*16;
            cp_async16(baseA + soff, A + (size_t)(m0+row)*lda + k0 + seg*8);
            cp_async16(baseB + soff, B + (size_t)(n0+row)*ldb + k0 + seg*8);
        }
        cp_commit();
    };

    load_chunk(0, 0);

    for (int c = 0; c < nc; c++) {
        const int stage = c & 1;
        cp_wait<0>();
        __syncthreads();
        if (c + 1 < nc) load_chunk(c+1, stage^1);

        const __half* At = reinterpret_cast<const __half*>(dsm + stage*STAGE16);
        const __half* Bt = At + TILE16/2;

        #pragma unroll
        for (int ks = 0; ks < 4; ks++) {
            wmma::fragment<wmma::matrix_b, 16,16,16, __half, wmma::col_major> bfr[2];
            #pragma unroll
            for (int nt = 0; nt < 2; nt++)
                wmma::load_matrix_sync(bfr[nt], Bt + (wn*32 + nt*16)*TSTR + ks*16, TSTR);
            wmma::fragment<wmma::matrix_a, 16,16,16, __half, wmma::row_major> af[4];
            #pragma unroll
            for (int mt = 0; mt < 4; mt++)
                wmma::load_matrix_sync(af[mt], At + (wm*64 + mt*16)*TSTR + ks*16, TSTR);
            #pragma unroll
            for (int mt = 0; mt < 4; mt++)
                #pragma unroll
                for (int nt = 0; nt < 2; nt++)
                    wmma::mma_sync(acc[mt][nt], af[mt], bfr[nt], acc[mt][nt]);
        }
    }
    __syncthreads();

    const float* bp = nullptr;
    int bbase = 0;
    if (BMODE == 1) { bp = b0; bbase = n0; }
    if (BMODE == 2) {
        int sel = blockIdx.x >> 1;
        bp = (sel == 0) ? b0 : ((sel == 1) ? b1p : b2p);
        bbase = (blockIdx.x & 1) * 128;
    }

    float* stg = reinterpret_cast<float*>(dsm);
    #pragma unroll
    for (int mt = 0; mt < 4; mt++)
        #pragma unroll
        for (int nt = 0; nt < 2; nt++)
            wmma::store_matrix_sync(stg + (wm*64 + mt*16)*136 + wn*32 + nt*16,
                                    acc[mt][nt], 136, wmma::mem_row_major);
    __syncthreads();

    int row = tid >> 1;
    int cb  = (tid & 1) * 64;
    const float* sr = stg + row*136 + cb;
    size_t crow = (size_t)(m0+row)*Ntot + n0 + cb;
    #pragma unroll
    for (int j = 0; j < 64; j += 4) {
        float4 v = *reinterpret_cast<const float4*>(sr + j);
        if (BMODE) {
            float4 b = *reinterpret_cast<const float4*>(bp + bbase + cb + j);
            v.x += b.x; v.y += b.y; v.z += b.z; v.w += b.w;
        }
        if (RELU) {
            v.x = fmaxf(v.x, 0.f); v.y = fmaxf(v.y, 0.f);
            v.z = fmaxf(v.z, 0.f); v.w = fmaxf(v.w, 0.f);
        }
        if (WF32) *reinterpret_cast<float4*>(C + crow + j) = v;
        if (WHALF) {
            __half2 h01 = __floats2half2_rn(v.x, v.y);
            __half2 h23 = __floats2half2_rn(v.z, v.w);
            __half* hp = Ch + crow;
            *reinterpret_cast<__half2*>(hp + j)     = h01;
            *reinterpret_cast<__half2*>(hp + j + 2) = h23;
        }
    }
}

// ---------------- sparse GCN aggregation (+bias +relu) ----------------------
template<bool WF32>
__global__ void __launch_bounds__(256)
agg_csr(const float* __restrict__ xw, const int* __restrict__ rp,
        const int* __restrict__ ci, const float* __restrict__ wv,
        const float* __restrict__ bias, float* __restrict__ outf,
        __half* __restrict__ sp)
{
    int warp = blockIdx.x*8 + (threadIdx.x >> 5);
    int lane = threadIdx.x & 31;
    int p = warp & 127;
    size_t gbase = (size_t)(warp & ~127) * Dn;

    float4 a0 = make_float4(0.f,0.f,0.f,0.f);
    float4 a1 = make_float4(0.f,0.f,0.f,0.f);
    int s0 = rp[p], s1 = rp[p+1];
    for (int e = s0; e < s1; e++) {
        int src = ci[e]; float w = wv[e];
        const float4* rowp = reinterpret_cast<const float4*>(xw + gbase + (size_t)src*Dn);
        float4 x0 = rowp[lane];
        float4 x1 = rowp[lane+32];
        a0.x = fmaf(w, x0.x, a0.x); a0.y = fmaf(w, x0.y, a0.y);
        a0.z = fmaf(w, x0.z, a0.z); a0.w = fmaf(w, x0.w, a0.w);
        a1.x = fmaf(w, x1.x, a1.x); a1.y = fmaf(w, x1.y, a1.y);
        a1.z = fmaf(w, x1.z, a1.z); a1.w = fmaf(w, x1.w, a1.w);
    }
    int c0 = lane*4;
    float4 b0 = *reinterpret_cast<const float4*>(bias + c0);
    float4 b1 = *reinterpret_cast<const float4*>(bias + c0 + 128);
    a0.x = fmaxf(a0.x + b0.x, 0.f); a0.y = fmaxf(a0.y + b0.y, 0.f);
    a0.z = fmaxf(a0.z + b0.z, 0.f); a0.w = fmaxf(a0.w + b0.w, 0.f);
    a1.x = fmaxf(a1.x + b1.x, 0.f); a1.y = fmaxf(a1.y + b1.y, 0.f);
    a1.z = fmaxf(a1.z + b1.z, 0.f); a1.w = fmaxf(a1.w + b1.w, 0.f);

    if (WF32) {
        float* dst = outf + (size_t)warp*Dn;
        *reinterpret_cast<float4*>(dst + c0)       = a0;
        *reinterpret_cast<float4*>(dst + c0 + 128) = a1;
    }
    __half* sprow = sp + (size_t)warp*Dn;
    *reinterpret_cast<__half2*>(sprow + c0)     = __floats2half2_rn(a0.x, a0.y);
    *reinterpret_cast<__half2*>(sprow + c0 + 2) = __floats2half2_rn(a0.z, a0.w);
    *reinterpret_cast<__half2*>(sprow + c0 + 128) = __floats2half2_rn(a1.x, a1.y);
    *reinterpret_cast<__half2*>(sprow + c0 + 130) = __floats2half2_rn(a1.z, a1.w);
}

// ---------------- attention: f32x2-packed, fp16 output ----------------------
__global__ void __launch_bounds__(128)
attn_kernel(const float* __restrict__ qkv, __half* __restrict__ sp)
{
    int head = blockIdx.x;
    int g    = blockIdx.y;
    int tid  = threadIdx.x;

    __shared__ u64t Ks[Pn][HDn/2];
    __shared__ u64t Vs[Pn][HDn/2];

    size_t base = ((size_t)g*Pn + tid)*768 + head*HDn;
    u64t qr[HDn/2];
    #pragma unroll
    for (int j = 0; j < HDn/4; j++) {
        float4 qv = reinterpret_cast<const float4*>(qkv + base)[j];
        float4 kv = reinterpret_cast<const float4*>(qkv + base + 256)[j];
        float4 vv = reinterpret_cast<const float4*>(qkv + base + 512)[j];
        qr[2*j]   = f2pack(qv.x, qv.y);
        qr[2*j+1] = f2pack(qv.z, qv.w);
        Ks[tid][2*j]   = f2pack(kv.x, kv.y);
        Ks[tid][2*j+1] = f2pack(kv.z, kv.w);
        Vs[tid][2*j]   = f2pack(vv.x, vv.y);
        Vs[tid][2*j+1] = f2pack(vv.z, vv.w);
    }
    __syncthreads();

    const float scale = 0.17677669529663687f;
    float l = 0.f;
    u64t acc[HDn/2];
    #pragma unroll
    for (int d = 0; d < HDn/2; d++) acc[d] = 0ull;

    for (int j = 0; j < Pn; j++) {
        u64t s2 = 0ull;
        #pragma unroll
        for (int d = 0; d < HDn/2; d++) s2 = fma2(qr[d], Ks[j][d], s2);
        float2 sv = f2unpack(s2);
        float e = __expf((sv.x + sv.y)*scale);
        l += e;
        u64t ee = f2pack(e, e);
        #pragma unroll
        for (int d = 0; d < HDn/2; d++) acc[d] = fma2(ee, Vs[j][d], acc[d]);
    }
    float inv = 1.f / l;
    __half* sprow = sp + ((size_t)g*Pn + tid)*Dn + head*HDn;
    #pragma unroll
    for (int d = 0; d < HDn/2; d += 2) {
        float2 p0 = f2unpack(acc[d]);
        float2 p1 = f2unpack(acc[d+1]);
        *reinterpret_cast<__half2*>(sprow + 2*d)     = __floats2half2_rn(p0.x*inv, p0.y*inv);
        *reinterpret_cast<__half2*>(sprow + 2*d + 2) = __floats2half2_rn(p1.x*inv, p1.y*inv);
    }
}

// ---------------- LayerNorm(x + t)*g + b -------------------------------------
template<bool WHALF>
__global__ void __launch_bounds__(Dn)
ln_kernel(const float* __restrict__ x, const float* __restrict__ t,
          const float* __restrict__ gam, const float* __restrict__ bet,
          float* __restrict__ out, __half* __restrict__ sp)
{
    int row = blockIdx.x;
    int f   = threadIdx.x;
    size_t idx = (size_t)row*Dn + f;
    float v = x[idx] + t[idx];

    __shared__ float sh[8];
    int lane = f & 31, w = f >> 5;

    float s = v;
    #pragma unroll
    for (int off = 16; off > 0; off >>= 1) s += __shfl_xor_sync(0xffffffffu, s, off);
    if (lane == 0) sh[w] = s;
    __syncthreads();
    float mean = 0.f;
    #pragma unroll
    for (int i = 0; i < 8; i++) mean += sh[i];
    mean *= (1.f/Dn);

    float d  = v - mean;
    float s2 = d*d;
    #pragma unroll
    for (int off = 16; off > 0; off >>= 1) s2 += __shfl_xor_sync(0xffffffffu, s2, off);
    __syncthreads();
    if (lane == 0) sh[w] = s2;
    __syncthreads();
    float var = 0.f;
    #pragma unroll
    for (int i = 0; i < 8; i++) var += sh[i];
    var *= (1.f/Dn);

    float r = rsqrtf(var + 1e-5f);
    float o = d*r*gam[f] + bet[f];
    out[idx] = o;
    if (WHALF) sp[(size_t)row*Dn + f] = __float2half_rn(o);
}

// ---------------------------------------------------------------------------
extern "C" void kernel_launch(void* const* d_in, const int* in_sizes, int n_in,
                              void* d_out, int out_size)
{
    const float* x    = (const float*)d_in[0];
    const int*   ei   = (const int*)  d_in[1];
    const float* c1W  = (const float*)d_in[6];
    const float* c1b  = (const float*)d_in[7];
    const float* c2W  = (const float*)d_in[8];
    const float* c2b  = (const float*)d_in[9];
    const float* WqA  = (const float*)d_in[10];
    const float* bqA  = (const float*)d_in[11];
    const float* WkA  = (const float*)d_in[12];
    const float* bkA  = (const float*)d_in[13];
    const float* WvA  = (const float*)d_in[14];
    const float* bvA  = (const float*)d_in[15];
    const float* WoA  = (const float*)d_in[16];
    const float* boA  = (const float*)d_in[17];
    const float* W1A  = (const float*)d_in[18];
    const float* b1A  = (const float*)d_in[19];
    const float* W2A  = (const float*)d_in[20];
    const float* b2A  = (const float*)d_in[21];
    const float* l1gA = (const float*)d_in[22];
    const float* l1bA = (const float*)d_in[23];
    const float* l2gA = (const float*)d_in[24];
    const float* l2bA = (const float*)d_in[25];
    float* out = (float*)d_out;

    float *h, *tmp, *qkv, *wv;
    __half *x16, *a16, *f16, *w16;
    int *rp, *ci;
    cudaGetSymbolAddress((void**)&h,    g_h);
    cudaGetSymbolAddress((void**)&tmp,  g_tmp);
    cudaGetSymbolAddress((void**)&qkv,  g_qkv);
    cudaGetSymbolAddress((void**)&x16,  g_x16);
    cudaGetSymbolAddress((void**)&a16,  g_a16);
    cudaGetSymbolAddress((void**)&f16,  g_f16);
    cudaGetSymbolAddress((void**)&w16,  g_w16);
    cudaGetSymbolAddress((void**)&rp,   g_rp);
    cudaGetSymbolAddress((void**)&ci,   g_ci);
    cudaGetSymbolAddress((void**)&wv,   g_wv);

    cudaFuncSetAttribute(gemm16<0,false,true ,false>, cudaFuncAttributeMaxDynamicSharedMemorySize, GEMM16_SMEM);
    cudaFuncSetAttribute(gemm16<2,false,true ,false>, cudaFuncAttributeMaxDynamicSharedMemorySize, GEMM16_SMEM);
    cudaFuncSetAttribute(gemm16<1,false,true ,false>, cudaFuncAttributeMaxDynamicSharedMemorySize, GEMM16_SMEM);
    cudaFuncSetAttribute(gemm16<1,true ,false,true >, cudaFuncAttributeMaxDynamicSharedMemorySize, GEMM16_SMEM);

    // ---- launch 0: graph setup ----
    k_setup<<<1, Pn>>>(ei, rp, ci, wv);

    // ---- launch 1: all weight packs ([N][K] fp16) ----
    const long long oC1 = 0, oC2 = W16_CONV;
    const long long oL  = 2*W16_CONV;
    WPack wp;
    {
        int i = 0;
        long long s = 0;
        auto add = [&](const float* src, long long dst, int K, int N) {
            wp.d[i] = {src, dst, K, N};
            wp.start[i] = s;
            s += (long long)K*N;
            i++;
        };
        add(c1W, oC1, Dn, Dn);
        add(c2W, oC2, Dn, Dn);
        for (int l = 0; l < 2; l++) {
            long long b = oL + (long long)l*W16_LAYER;
            add(WqA + (size_t)l*65536,  b,              Dn, Dn);
            add(WkA + (size_t)l*65536,  b + W16_CONV,   Dn, Dn);
            add(WvA + (size_t)l*65536,  b + 2*W16_CONV, Dn, Dn);
            add(WoA + (size_t)l*65536,  b + 3*W16_CONV, Dn, Dn);
            add(W1A + (size_t)l*262144, b + 4*W16_CONV, Dn, DFn);
            add(W2A + (size_t)l*262144, b + 4*W16_CONV + W16_FFN, DFn, Dn);
        }
        wp.start[14] = s;
    }
    k_wprepAll<<<(int)((wp.start[14] + 255)/256), 256>>>(wp);

    // ---- launch 2: input convert ----
    k_acvt<<<(Mn*64)/256, 256>>>(x, x16);

    dim3 gD(2, Mn/128);      // N=256 GEMMs
    dim3 gQKV(6, Mn/128);    // N=768 fused QKV
    dim3 gF1(8, Mn/128);     // N=1024 FFN1

    // ---- GCN ----
    gemm16<0,false,true,false><<<gD, 256, GEMM16_SMEM>>>(x16, 256, w16 + oC1, 256, nullptr, nullptr, nullptr, tmp, nullptr, Dn, Dn);
    agg_csr<false><<<Mn/8, 256>>>(tmp, rp, ci, wv, c1b, nullptr, a16);
    gemm16<0,false,true,false><<<gD, 256, GEMM16_SMEM>>>(a16, 256, w16 + oC2, 256, nullptr, nullptr, nullptr, tmp, nullptr, Dn, Dn);
    agg_csr<true ><<<Mn/8, 256>>>(tmp, rp, ci, wv, c2b, h, a16);

    for (int l = 0; l < 2; l++) {
        long long b = oL + (long long)l*W16_LAYER;
        const float* bq = bqA + (size_t)l*Dn;
        const float* bk = bkA + (size_t)l*Dn;
        const float* bv = bvA + (size_t)l*Dn;
        const float* bo = boA + (size_t)l*Dn;
        const float* b1 = b1A + (size_t)l*DFn;
        const float* b2 = b2A + (size_t)l*Dn;
        const float* l1g = l1gA + (size_t)l*Dn; const float* l1b = l1bA + (size_t)l*Dn;
        const float* l2g = l2gA + (size_t)l*Dn; const float* l2b = l2bA + (size_t)l*Dn;

        gemm16<2,false,true,false><<<gQKV, 256, GEMM16_SMEM>>>(a16, 256, w16 + b, 256, bq, bk, bv, qkv, nullptr, Dn, 768);

        attn_kernel<<<dim3(Hn, Gn), 128>>>(qkv, a16);

        gemm16<1,false,true,false><<<gD, 256, GEMM16_SMEM>>>(a16, 256, w16 + b + 3*W16_CONV, 256, bo, nullptr, nullptr, tmp, nullptr, Dn, Dn);
        ln_kernel<true><<<Mn, Dn>>>(h, tmp, l1g, l1b, h, a16);

        gemm16<1,true,false,true><<<gF1, 256, GEMM16_SMEM>>>(a16, 256, w16 + b + 4*W16_CONV, 256, b1, nullptr, nullptr, nullptr, f16, Dn, DFn);
        gemm16<1,false,true,false><<<gD, 256, GEMM16_SMEM>>>(f16, 1024, w16 + b + 4*W16_CONV + W16_FFN, 1024, b2, nullptr, nullptr, tmp, nullptr, DFn, Dn);

        if (l == 0) ln_kernel<true ><<<Mn, Dn>>>(h, tmp, l2g, l2b, h, a16);
        else        ln_kernel<false><<<Mn, Dn>>>(h, tmp, l2g, l2b, out, nullptr);
    }
}